// round 17
// baseline (speedup 1.0000x reference)
#include <cuda_runtime.h>
#include <stdint.h>

// MessagePassing: out[dst[e]] += x[src[e]], N=100000, E=1600000, D=32 fp32.
// edge_index stored as int32 [2, E] (JAX x64-disabled). Row 0 = src, row 1 = dst.
//
// CONVERGED STRUCTURE (best measured: 41.28us total, scatter 37.8us).
// 8 lanes per group cover one 128B feature row (float4/lane). Each group
// processes EPT=8 edges: indices loaded as int4, all 8 gathers issued before
// any RED (MLP=8), scatter via red.global.add.v4.f32 (max RED width on
// sm_103a). Per-edge: 1 gather wavefront + 1 RED wavefront = structural min.
// This round: block 256 -> 128 (finer last-wave balancing; only untested
// launch shape). Convergence evidence: fp16 gathers -2% (wavefront-bound,
// not byte-bound); EPT=16 and block=512 regress/tie; 6 sort restructures
// lost to reorder cost; v8.f32 RED rejected by ptxas.

#define D_FEAT 32
#define CHUNKS 8   // D_FEAT / 4
#define EPT    8   // edges per thread-group

__global__ void mp_zero_kernel(float4* __restrict__ out, long n4) {
    long i = (long)blockIdx.x * blockDim.x + threadIdx.x;
    if (i < n4) out[i] = make_float4(0.f, 0.f, 0.f, 0.f);
}

__device__ __forceinline__ void red_add_v4(float* p, float4 v) {
    asm volatile("red.global.add.v4.f32 [%0], {%1, %2, %3, %4};"
                 :: "l"(p), "f"(v.x), "f"(v.y), "f"(v.z), "f"(v.w)
                 : "memory");
}

__global__ void __launch_bounds__(128)
mp_scatter_kernel(const float4* __restrict__ x,
                  const int* __restrict__ src,
                  const int* __restrict__ dst,
                  float* __restrict__ out,
                  long n_edges) {
    long t = (long)blockIdx.x * blockDim.x + threadIdx.x;
    long g = t >> 3;          // edge-group index
    int  c = (int)(t & 7);    // 16B chunk within the 128B feature row
    long e0 = g * EPT;
    if (e0 >= n_edges) return;

    if (e0 + EPT <= n_edges) {
        // Vectorized index loads: e0 is a multiple of 8 -> 16B aligned.
        int4 sa = __ldg((const int4*)(src + e0));
        int4 sb = __ldg((const int4*)(src + e0 + 4));
        int4 da = __ldg((const int4*)(dst + e0));
        int4 db = __ldg((const int4*)(dst + e0 + 4));

        // Batch all 8 gathers (MLP=8) before any RED.
        float4 v0 = __ldg(&x[(long)sa.x * CHUNKS + c]);
        float4 v1 = __ldg(&x[(long)sa.y * CHUNKS + c]);
        float4 v2 = __ldg(&x[(long)sa.z * CHUNKS + c]);
        float4 v3 = __ldg(&x[(long)sa.w * CHUNKS + c]);
        float4 v4 = __ldg(&x[(long)sb.x * CHUNKS + c]);
        float4 v5 = __ldg(&x[(long)sb.y * CHUNKS + c]);
        float4 v6 = __ldg(&x[(long)sb.z * CHUNKS + c]);
        float4 v7 = __ldg(&x[(long)sb.w * CHUNKS + c]);

        int co = c * 4;
        red_add_v4(out + (long)da.x * D_FEAT + co, v0);
        red_add_v4(out + (long)da.y * D_FEAT + co, v1);
        red_add_v4(out + (long)da.z * D_FEAT + co, v2);
        red_add_v4(out + (long)da.w * D_FEAT + co, v3);
        red_add_v4(out + (long)db.x * D_FEAT + co, v4);
        red_add_v4(out + (long)db.y * D_FEAT + co, v5);
        red_add_v4(out + (long)db.z * D_FEAT + co, v6);
        red_add_v4(out + (long)db.w * D_FEAT + co, v7);
    } else {
        // Tail: scalar loop over remaining edges (not taken for E=1.6M).
        for (long e = e0; e < n_edges; ++e) {
            int s = __ldg(&src[e]);
            int d = __ldg(&dst[e]);
            float4 v = __ldg(&x[(long)s * CHUNKS + c]);
            red_add_v4(out + (long)d * D_FEAT + c * 4, v);
        }
    }
}

extern "C" void kernel_launch(void* const* d_in, const int* in_sizes, int n_in,
                              void* d_out, int out_size) {
    const float4* x   = (const float4*)d_in[0];
    const int*    ei  = (const int*)d_in[1];
    long n_edges = (long)in_sizes[1] / 2;      // edge_index has 2*E elements
    const int* src = ei;                       // row 0
    const int* dst = ei + n_edges;             // row 1
    float* out = (float*)d_out;

    // Zero the (poisoned) output.
    long n4 = (long)out_size / 4;
    {
        int threads = 256;
        long blocks = (n4 + threads - 1) / threads;
        mp_zero_kernel<<<(unsigned)blocks, threads>>>((float4*)out, n4);
    }

    // Scatter-add: 8 lanes per edge-group, 8 edges per group, block 128.
    {
        long total = ((n_edges + EPT - 1) / EPT) * 8;
        int threads = 128;
        long blocks = (total + threads - 1) / threads;
        mp_scatter_kernel<<<(unsigned)blocks, threads>>>(x, src, dst, out, n_edges);
    }
}